// round 14
// baseline (speedup 1.0000x reference)
#include <cuda_runtime.h>
#include <cuda_fp16.h>
#include <cstdint>

#define NMAX 50048
#define EMAX 400000

__device__ float g_denom[NMAX];
__device__ float g_aggr[(size_t)NMAX * 128];
__device__ __align__(16) __half g_nodes_h[(size_t)NMAX * 128];
__device__ __align__(16) __half g_edges_h[(size_t)EMAX * 16];
// packed fp16 weights: per 16-K slab, [NOUT][32B] rows, XOR-swizzled halves
__device__ __align__(16) unsigned char g_wpack[729088];

#define OFF_MW1 0u
#define OFF_MW2 139264u
#define OFF_MW3 270336u
#define OFF_AW1 335872u
#define OFF_AW2 368640u
#define OFF_UW1 401408u
#define OFF_UW2 532480u
#define OFF_UW3 663552u

__device__ __forceinline__ uint32_t smem_u32(const void* p) {
    return (uint32_t)__cvta_generic_to_shared(p);
}
__device__ __forceinline__ void ldsm4(uint32_t& r0, uint32_t& r1,
                                      uint32_t& r2, uint32_t& r3, uint32_t a) {
    asm volatile("ldmatrix.sync.aligned.m8n8.x4.shared.b16 {%0,%1,%2,%3}, [%4];"
                 : "=r"(r0), "=r"(r1), "=r"(r2), "=r"(r3) : "r"(a));
}
__device__ __forceinline__ void mma_f16(float c[4],
    uint32_t a0, uint32_t a1, uint32_t a2, uint32_t a3, uint32_t b0, uint32_t b1)
{
    asm volatile(
        "mma.sync.aligned.m16n8k16.row.col.f32.f16.f16.f32 "
        "{%0,%1,%2,%3}, {%4,%5,%6,%7}, {%8,%9}, {%0,%1,%2,%3};"
        : "+f"(c[0]), "+f"(c[1]), "+f"(c[2]), "+f"(c[3])
        : "r"(a0), "r"(a1), "r"(a2), "r"(a3), "r"(b0), "r"(b1));
}

#define WSTAGE 1024
#define WREGION 3072

// B-row swizzled byte offset (32 B rows, halves XOR bit2 of row)
__device__ __forceinline__ uint32_t bswz(int row, int h) {
    return (uint32_t)(row * 32 + ((h ^ ((row >> 2) & 1)) << 4));
}

// ---------------------------------------------------------------------------
// Warp-autonomous fp16 MLP layer over MT*16 rows, 8 warps, with a
// CONTINUOUS cross-layer weight ring: tail issues prefetch the NEXT layer's
// first 3 slab strips; `ring` carries the buffer phase across layers.
// Invariant: slab j of a layer lives in buffer (ring_at_entry + j) % 3,
// whether issued by prime (first layer) or the previous layer's tail.
// ---------------------------------------------------------------------------
template<int K, int NOUT, bool RELU, int LDIN, int LDOUT, int MT>
__device__ __forceinline__ void mma_layer(
    const __half* __restrict__ sIn, const unsigned char* __restrict__ Wp,
    const float* __restrict__ Bv, __half* __restrict__ sOut,
    unsigned char* __restrict__ sWbase,
    float* __restrict__ gOut, int row0, int rowlim,
    const unsigned char* __restrict__ nxtW, int nxtNW, int nxtNSLAB,
    int& ring, bool prime)
{
    constexpr int NSLAB = K / 16;
    constexpr int NW = NOUT / 8;
    constexpr int NT = NW / 8;
    constexpr int WCH = NW * 2;
    const int tid = threadIdx.x, lane = tid & 31, warp = tid >> 5;
    const int n0 = warp * NW;
    unsigned char* wb = sWbase + warp * WREGION;
    const int g = lane >> 2, tg = lane & 3;
    const int a_row = (lane & 7) + ((lane >> 3) & 1) * 8;
    const int a_k   = (lane >> 4) * 8;
    const int b_n   = ((lane >> 4) & 1) * 8 + (lane & 7);
    const int b_h   = (lane >> 3) & 1;

    auto issue_cur = [&](int s, int buf) {
        const unsigned char* src = Wp + ((size_t)s * NOUT + n0) * 32;
        unsigned char* dst = wb + buf * WSTAGE;
#pragma unroll
        for (int c = lane; c < WCH; c += 32) {
            uint32_t da = smem_u32(dst + c * 16);
            asm volatile("cp.async.ca.shared.global [%0], [%1], 16;"
                         :: "r"(da), "l"(src + c * 16));
        }
        asm volatile("cp.async.commit_group;");
    };
    auto issue_nxt = [&](int j, int buf) {
        if (nxtW != nullptr && j < nxtNSLAB) {
            const int nNOUT = nxtNW * 8;
            const unsigned char* src = nxtW + ((size_t)j * nNOUT + warp * nxtNW) * 32;
            unsigned char* dst = wb + buf * WSTAGE;
            for (int c = lane; c < nxtNW * 2; c += 32) {
                uint32_t da = smem_u32(dst + c * 16);
                asm volatile("cp.async.ca.shared.global [%0], [%1], 16;"
                             :: "r"(da), "l"(src + c * 16));
            }
        }
        asm volatile("cp.async.commit_group;");
    };

    if (prime) {
        issue_cur(0, ring % 3);
        issue_cur(1, (ring + 1) % 3);
        issue_cur(2, (ring + 2) % 3);
    }
    __syncthreads();   // sIn ready

    float acc[MT][NT][4];
#pragma unroll
    for (int mt = 0; mt < MT; mt++)
#pragma unroll
        for (int nt = 0; nt < NT; nt++)
#pragma unroll
            for (int q = 0; q < 4; q++) acc[mt][nt][q] = 0.f;

    for (int s = 0; s < NSLAB; s++) {
        asm volatile("cp.async.wait_group 2;" ::: "memory");
        __syncwarp();
        const unsigned char* buf = wb + ((ring + s) % 3) * WSTAGE;
        const int kc = s * 16;
#pragma unroll
        for (int ng = 0; ng < NT / 2; ng++) {
            uint32_t B0, B1, B2, B3;
            ldsm4(B0, B1, B2, B3, smem_u32(buf + bswz(ng * 16 + b_n, b_h)));
#pragma unroll
            for (int mt = 0; mt < MT; mt++) {
                uint32_t A0, A1, A2, A3;
                ldsm4(A0, A1, A2, A3,
                      smem_u32(sIn + (mt * 16 + a_row) * LDIN + kc + a_k));
                mma_f16(acc[mt][2 * ng],     A0, A1, A2, A3, B0, B1);
                mma_f16(acc[mt][2 * ng + 1], A0, A1, A2, A3, B2, B3);
            }
        }
        const int t = s + 3;
        if (t < NSLAB) issue_cur(t, (ring + t) % 3);
        else           issue_nxt(t - NSLAB, (ring + t) % 3);
    }
    ring = (ring + NSLAB) % 3;

#pragma unroll
    for (int nt = 0; nt < NT; nt++) {
        int c = n0 + nt * 8 + 2 * tg;
        float b0 = __ldg(Bv + c), b1 = __ldg(Bv + c + 1);
#pragma unroll
        for (int mt = 0; mt < MT; mt++) {
#pragma unroll
            for (int h = 0; h < 2; h++) {
                int r = mt * 16 + g + h * 8;
                float v0 = acc[mt][nt][h * 2 + 0] + b0;
                float v1 = acc[mt][nt][h * 2 + 1] + b1;
                if (RELU) { v0 = fmaxf(v0, 0.f); v1 = fmaxf(v1, 0.f); }
                *(__half2*)(sOut + r * LDOUT + c) = __floats2half2_rn(v0, v1);
                if (gOut != nullptr && row0 + r < rowlim)
                    *(float2*)(gOut + (size_t)(row0 + r) * NOUT + c) =
                        make_float2(v0, v1);
            }
        }
    }
    __syncthreads();
}

// ---------------------------------------------------------------------------
// G2 variant over MT*16 rows: gate dot folded into epilogue. Ring-continuous
// (no next layer; tail commits empty groups).
// ---------------------------------------------------------------------------
template<int K, int LDIN, int MT>
__device__ __forceinline__ void mma_layer_dot(
    const __half* __restrict__ sIn, const unsigned char* __restrict__ Wp,
    const float* __restrict__ Bv, const float* __restrict__ aw3,
    float* __restrict__ sdot, unsigned char* __restrict__ sWbase,
    int& ring)
{
    constexpr int NOUT = 128, NSLAB = K / 16, NW = 16, NT = 2;
    const int tid = threadIdx.x, lane = tid & 31, warp = tid >> 5;
    const int n0 = warp * NW;
    unsigned char* wb = sWbase + warp * WREGION;
    const int g = lane >> 2, tg = lane & 3;
    const int a_row = (lane & 7) + ((lane >> 3) & 1) * 8;
    const int a_k   = (lane >> 4) * 8;
    const int b_n   = ((lane >> 4) & 1) * 8 + (lane & 7);
    const int b_h   = (lane >> 3) & 1;

    __syncthreads();   // sIn ready (slabs 0-2 pre-issued by previous layer)

    float acc[MT][NT][4];
#pragma unroll
    for (int mt = 0; mt < MT; mt++)
#pragma unroll
        for (int nt = 0; nt < NT; nt++)
#pragma unroll
            for (int q = 0; q < 4; q++) acc[mt][nt][q] = 0.f;

    for (int s = 0; s < NSLAB; s++) {
        asm volatile("cp.async.wait_group 2;" ::: "memory");
        __syncwarp();
        const unsigned char* buf = wb + ((ring + s) % 3) * WSTAGE;
        const int kc = s * 16;
        uint32_t B0, B1, B2, B3;
        ldsm4(B0, B1, B2, B3, smem_u32(buf + bswz(b_n, b_h)));
#pragma unroll
        for (int mt = 0; mt < MT; mt++) {
            uint32_t A0, A1, A2, A3;
            ldsm4(A0, A1, A2, A3,
                  smem_u32(sIn + (mt * 16 + a_row) * LDIN + kc + a_k));
            mma_f16(acc[mt][0], A0, A1, A2, A3, B0, B1);
            mma_f16(acc[mt][1], A0, A1, A2, A3, B2, B3);
        }
        const int t = s + 3;
        if (t < NSLAB) {
            const unsigned char* src = Wp + ((size_t)t * NOUT + n0) * 32;
            unsigned char* dst = wb + ((ring + t) % 3) * WSTAGE;
#pragma unroll
            for (int c = lane; c < NW * 2; c += 32) {
                uint32_t da = smem_u32(dst + c * 16);
                asm volatile("cp.async.ca.shared.global [%0], [%1], 16;"
                             :: "r"(da), "l"(src + c * 16));
            }
        }
        asm volatile("cp.async.commit_group;");
    }
    ring = (ring + NSLAB) % 3;

    float dp[MT][2];
#pragma unroll
    for (int mt = 0; mt < MT; mt++) { dp[mt][0] = 0.f; dp[mt][1] = 0.f; }
#pragma unroll
    for (int nt = 0; nt < NT; nt++) {
        int c = n0 + nt * 8 + 2 * tg;
        float b0 = __ldg(Bv + c), b1 = __ldg(Bv + c + 1);
        float a0 = __ldg(aw3 + c), a1 = __ldg(aw3 + c + 1);
#pragma unroll
        for (int mt = 0; mt < MT; mt++) {
#pragma unroll
            for (int h = 0; h < 2; h++) {
                float v0 = acc[mt][nt][h * 2 + 0] + b0;
                float v1 = acc[mt][nt][h * 2 + 1] + b1;
                dp[mt][h] += v0 * a0 + v1 * a1;
            }
        }
    }
#pragma unroll
    for (int mt = 0; mt < MT; mt++)
#pragma unroll
        for (int h = 0; h < 2; h++) {
            dp[mt][h] += __shfl_xor_sync(0xffffffffu, dp[mt][h], 1);
            dp[mt][h] += __shfl_xor_sync(0xffffffffu, dp[mt][h], 2);
            if (tg == 0) {
                int r = mt * 16 + g + h * 8;
                sdot[r * 8 + warp] = dp[mt][h];
            }
        }
    __syncthreads();
}

// ---------------------------------------------------------------------------
// Fused pack + init kernel: weights -> swizzled fp16; nodes/edges -> fp16.
// ---------------------------------------------------------------------------
__device__ __forceinline__ void pack_one(const float* src, int idx, int N,
                                         unsigned int off) {
    int k = idx / N, n = idx - k * N;
    int s = k >> 4, h = (k >> 3) & 1, e = k & 7;
    uint32_t b = off + (uint32_t)(s * N + n) * 32u
               + (uint32_t)((h ^ ((n >> 2) & 1)) << 4) + (uint32_t)(e * 2);
    *(__half*)(g_wpack + b) = __float2half_rn(src[idx]);
}
__global__ void pack_init_kernel(
    const float* __restrict__ mw1, const float* __restrict__ mw2,
    const float* __restrict__ mw3, const float* __restrict__ aw1,
    const float* __restrict__ aw2, const float* __restrict__ uw1,
    const float* __restrict__ uw2, const float* __restrict__ uw3,
    const float* __restrict__ nodes, const float* __restrict__ edges,
    int N, int E)
{
    int idx = blockIdx.x * blockDim.x + threadIdx.x;
    if      (idx <  69632) pack_one(mw1, idx,          256, OFF_MW1);
    else if (idx < 135168) pack_one(mw2, idx -  69632, 256, OFF_MW2);
    else if (idx < 167936) pack_one(mw3, idx - 135168, 128, OFF_MW3);
    else if (idx < 184320) pack_one(aw1, idx - 167936, 128, OFF_AW1);
    else if (idx < 200704) pack_one(aw2, idx - 184320, 128, OFF_AW2);
    else if (idx < 266240) pack_one(uw1, idx - 200704, 256, OFF_UW1);
    else if (idx < 331776) pack_one(uw2, idx - 266240, 256, OFF_UW2);
    else if (idx < 364544) pack_one(uw3, idx - 331776, 128, OFF_UW3);
    if (idx < N * 128) {
        g_nodes_h[idx] = __float2half_rn(nodes[idx]);
        g_aggr[idx] = 0.f;
    }
    if (idx < E * 16) g_edges_h[idx] = __float2half_rn(edges[idx]);
    if (idx < N) g_denom[idx] = 0.f;
}

// ---------------------------------------------------------------------------
// edge kernel: 128 edges/CTA, ring-continuous weights, fp16 gather.
// smem: sA 71680 | sB 67584 | sW 24576 | sdot 4096 | swexp 512 = 168448 B
// ---------------------------------------------------------------------------
__global__ __launch_bounds__(256, 1)
void edge_kernel(
    const int* __restrict__ senders, const int* __restrict__ receivers,
    const float* __restrict__ b1, const float* __restrict__ b2,
    const float* __restrict__ b3, const float* __restrict__ ab1,
    const float* __restrict__ ab2,
    const float* __restrict__ aw3, const float* __restrict__ ab3, int E)
{
    extern __shared__ unsigned char smem[];
    __half* sA = (__half*)smem;                    // stride 280 (or 136)
    __half* sB = (__half*)(smem + 71680);          // stride 264 (or 136)
    unsigned char* sW = smem + 139264;
    float* sdot = (float*)(smem + 163840);         // [128][8]
    float* swexp = (float*)(smem + 167936);        // [128]

    const int tid = threadIdx.x, lane = tid & 31, warp = tid >> 5;
    const int e0 = blockIdx.x * 128;
    const int hsel = lane >> 4, l = lane & 15;

    // gather (pure fp16 copy): [edge(16h) | node[s](128h) | node[r](128h)]
#pragma unroll
    for (int i = 0; i < 16; i++) {
        int e = warp * 16 + i;
        int eg = e0 + e;
        int egc = eg < E ? eg : E - 1;
        int s = senders[egc], r = receivers[egc];
        __half* dst = sA + e * 280;
        int idx = hsel ? r : s;
        uint4 v = *(const uint4*)(g_nodes_h + (size_t)idx * 128 + l * 8);
        *(uint4*)(dst + 16 + hsel * 128 + l * 8) = v;
        if (lane < 2) {
            uint4 ev = *(const uint4*)(g_edges_h + (size_t)egc * 16 + lane * 8);
            *(uint4*)(dst + lane * 8) = ev;
        }
    }

    int ring = 0;
    mma_layer<272, 256, true , 280, 264, 8>(sA, g_wpack + OFF_MW1, b1, sB, sW,
        nullptr, 0, 0, g_wpack + OFF_MW2, 32, 16, ring, true);
    mma_layer<256, 256, false, 264, 280, 8>(sB, g_wpack + OFF_MW2, b2, sA, sW,
        nullptr, 0, 0, g_wpack + OFF_MW3, 16, 16, ring, false);
    mma_layer<256, 128, false, 280, 136, 8>(sA, g_wpack + OFF_MW3, b3, sB, sW,
        nullptr, 0, 0, g_wpack + OFF_AW1, 16, 8, ring, false);
    mma_layer<128, 128, true , 136, 136, 8>(sB, g_wpack + OFF_AW1, ab1, sA, sW,
        nullptr, 0, 0, g_wpack + OFF_AW2, 16, 8, ring, false);
    mma_layer_dot<128, 136, 8>(sA, g_wpack + OFF_AW2, ab2, aw3, sdot, sW, ring);

    // finalize gates: w = exp(gate) (max-free softmax)
    if (tid < 128) {
        int eg = e0 + tid;
        float w = 0.f;
        if (eg < E) {
            float gate = __ldg(ab3);
#pragma unroll
            for (int j = 0; j < 8; j++) gate += sdot[tid * 8 + j];
            w = expf(gate);
            atomicAdd(&g_denom[receivers[eg]], w);
        }
        swexp[tid] = w;
    }
    __syncthreads();

    // scatter: aggr[recv] += w * msg (vector red, fp16 msgs in sB stride 136)
#pragma unroll
    for (int i = 0; i < 16; i++) {
        int e = warp * 16 + i;
        int eg = e0 + e;
        if (eg >= E) continue;
        float w = swexp[e];
        int r = receivers[eg];
        __half2 p0 = *(__half2*)(sB + e * 136 + lane * 4);
        __half2 p1 = *(__half2*)(sB + e * 136 + lane * 4 + 2);
        float2 f0 = __half22float2(p0), f1 = __half22float2(p1);
        float* dst = g_aggr + (size_t)r * 128 + lane * 4;
        asm volatile("red.global.add.v4.f32 [%0], {%1, %2, %3, %4};"
                     :: "l"(dst), "f"(w * f0.x), "f"(w * f0.y),
                        "f"(w * f1.x), "f"(w * f1.y) : "memory");
    }
}

// ---------------------------------------------------------------------------
// node kernel: 64-row/2-CTA config, ring-continuous weights.
// smem: sA 33792 | sB 33792 | sW 24576 = 92160 B
// ---------------------------------------------------------------------------
__global__ __launch_bounds__(256, 2)
void node_kernel(
    const float* __restrict__ ub1, const float* __restrict__ ub2,
    const float* __restrict__ ub3, float* __restrict__ out, int N)
{
    extern __shared__ unsigned char smem[];
    __half* sA = (__half*)smem;                    // stride 264
    __half* sB = (__half*)(smem + 33792);
    unsigned char* sW = smem + 67584;

    const int tid = threadIdx.x, lane = tid & 31, warp = tid >> 5;
    const int n0 = blockIdx.x * 64;

#pragma unroll
    for (int i = 0; i < 8; i++) {
        int e = warp * 8 + i;
        int n = n0 + e;
        __half* dst = sA + e * 264;
        if (n < N) {
            if (lane < 16) {
                uint4 v = *(const uint4*)(g_nodes_h + (size_t)n * 128 + lane * 8);
                *(uint4*)(dst + lane * 8) = v;
            }
            float d = g_denom[n];
            float inv = d > 0.f ? 1.f / d : 0.f;
            float4 v1 = *(const float4*)(g_aggr + (size_t)n * 128 + lane * 4);
            *(__half2*)(dst + 128 + lane * 4)     = __floats2half2_rn(inv * v1.x, inv * v1.y);
            *(__half2*)(dst + 128 + lane * 4 + 2) = __floats2half2_rn(inv * v1.z, inv * v1.w);
        } else {
            if (lane < 16) {
                uint4 z = make_uint4(0u, 0u, 0u, 0u);
                *(uint4*)(dst + lane * 8) = z;
            }
            *(float2*)(dst + 128 + lane * 4) = make_float2(0.f, 0.f);
        }
    }

    int ring = 0;
    mma_layer<256, 256, true , 264, 264, 4>(sA, g_wpack + OFF_UW1, ub1, sB, sW,
        nullptr, 0, 0, g_wpack + OFF_UW2, 32, 16, ring, true);
    mma_layer<256, 256, false, 264, 264, 4>(sB, g_wpack + OFF_UW2, ub2, sA, sW,
        nullptr, 0, 0, g_wpack + OFF_UW3, 16, 16, ring, false);
    mma_layer<256, 128, false, 264, 136, 4>(sA, g_wpack + OFF_UW3, ub3, sB, sW,
        out, n0, N, nullptr, 0, 0, ring, false);
}

// ---------------------------------------------------------------------------
extern "C" void kernel_launch(void* const* d_in, const int* in_sizes, int n_in,
                              void* d_out, int out_size)
{
    const float* nodes     = (const float*)d_in[0];
    const float* edges     = (const float*)d_in[1];
    const int*   senders   = (const int*)  d_in[2];
    const int*   receivers = (const int*)  d_in[3];
    const float* mw1 = (const float*)d_in[4];  const float* mb1 = (const float*)d_in[5];
    const float* mw2 = (const float*)d_in[6];  const float* mb2 = (const float*)d_in[7];
    const float* mw3 = (const float*)d_in[8];  const float* mb3 = (const float*)d_in[9];
    const float* aw1 = (const float*)d_in[10]; const float* ab1 = (const float*)d_in[11];
    const float* aw2 = (const float*)d_in[12]; const float* ab2 = (const float*)d_in[13];
    const float* aw3 = (const float*)d_in[14]; const float* ab3 = (const float*)d_in[15];
    const float* uw1 = (const float*)d_in[16]; const float* ub1 = (const float*)d_in[17];
    const float* uw2 = (const float*)d_in[18]; const float* ub2 = (const float*)d_in[19];
    const float* uw3 = (const float*)d_in[20]; const float* ub3 = (const float*)d_in[21];
    float* out = (float*)d_out;

    const int N = in_sizes[0] / 128;
    const int E = in_sizes[2];

    const int EDGE_SMEM = 168448;
    const int NODE_SMEM = 92160;
    cudaFuncSetAttribute(edge_kernel, cudaFuncAttributeMaxDynamicSharedMemorySize, EDGE_SMEM);
    cudaFuncSetAttribute(node_kernel, cudaFuncAttributeMaxDynamicSharedMemorySize, NODE_SMEM);

    int work = N * 128 > E * 16 ? N * 128 : E * 16;
    pack_init_kernel<<<(work + 255) / 256, 256>>>(
        mw1, mw2, mw3, aw1, aw2, uw1, uw2, uw3, nodes, edges, N, E);

    edge_kernel<<<(E + 127) / 128, 256, EDGE_SMEM>>>(
        senders, receivers, mb1, mb2, mb3, ab1, ab2, aw3, ab3, E);

    node_kernel<<<(N + 63) / 64, 256, NODE_SMEM>>>(
        ub1, ub2, ub3, out, N);
}

// round 15
// speedup vs baseline: 1.0317x; 1.0317x over previous
#include <cuda_runtime.h>
#include <cuda_fp16.h>
#include <cstdint>

#define NMAX 50048
#define EMAX 400000

__device__ float g_denom[NMAX];
__device__ float g_aggr[(size_t)NMAX * 128];
// packed fp16 weights: per 16-K slab, [NOUT][32B] rows, XOR-swizzled halves
__device__ __align__(16) unsigned char g_wpack[729088];

#define OFF_MW1 0u
#define OFF_MW2 139264u
#define OFF_MW3 270336u
#define OFF_AW1 335872u
#define OFF_AW2 368640u
#define OFF_UW1 401408u
#define OFF_UW2 532480u
#define OFF_UW3 663552u

__device__ __forceinline__ uint32_t smem_u32(const void* p) {
    return (uint32_t)__cvta_generic_to_shared(p);
}
__device__ __forceinline__ void ldsm4(uint32_t& r0, uint32_t& r1,
                                      uint32_t& r2, uint32_t& r3, uint32_t a) {
    asm volatile("ldmatrix.sync.aligned.m8n8.x4.shared.b16 {%0,%1,%2,%3}, [%4];"
                 : "=r"(r0), "=r"(r1), "=r"(r2), "=r"(r3) : "r"(a));
}
__device__ __forceinline__ void mma_f16(float c[4],
    uint32_t a0, uint32_t a1, uint32_t a2, uint32_t a3, uint32_t b0, uint32_t b1)
{
    asm volatile(
        "mma.sync.aligned.m16n8k16.row.col.f32.f16.f16.f32 "
        "{%0,%1,%2,%3}, {%4,%5,%6,%7}, {%8,%9}, {%0,%1,%2,%3};"
        : "+f"(c[0]), "+f"(c[1]), "+f"(c[2]), "+f"(c[3])
        : "r"(a0), "r"(a1), "r"(a2), "r"(a3), "r"(b0), "r"(b1));
}

#define WSTAGE 1024
#define WREGION 3072

// B-row swizzled byte offset (32 B rows, halves XOR bit2 of row)
__device__ __forceinline__ uint32_t bswz(int row, int h) {
    return (uint32_t)(row * 32 + ((h ^ ((row >> 2) & 1)) << 4));
}

// Prime helper: issue slabs 0..2 of a layer's per-warp strip (3 commit groups).
// Must match mma_layer's issue() exactly: buffer s%3, flat 16B chunks.
template<int NOUT>
__device__ __forceinline__ void prime_weights(
    const unsigned char* __restrict__ Wp, unsigned char* __restrict__ sWbase)
{
    constexpr int NW = NOUT / 8;
    constexpr int WCH = NW * 2;
    const int lane = threadIdx.x & 31, warp = threadIdx.x >> 5;
    unsigned char* wb = sWbase + warp * WREGION;
#pragma unroll
    for (int s = 0; s < 3; s++) {
        const unsigned char* src = Wp + ((size_t)s * NOUT + warp * NW) * 32;
        unsigned char* dst = wb + s * WSTAGE;
#pragma unroll
        for (int c = lane; c < WCH; c += 32) {
            uint32_t da = smem_u32(dst + c * 16);
            asm volatile("cp.async.ca.shared.global [%0], [%1], 16;"
                         :: "r"(da), "l"(src + c * 16));
        }
        asm volatile("cp.async.commit_group;");
    }
}

// ---------------------------------------------------------------------------
// Warp-autonomous fp16 MLP layer over MT*16 rows, 8 warps (R13-proven).
// PRIME=false when the kernel pre-issued slabs 0..2 (same commit count).
// ---------------------------------------------------------------------------
template<int K, int NOUT, bool RELU, int LDIN, int LDOUT, int MT, bool PRIME>
__device__ __forceinline__ void mma_layer(
    const __half* __restrict__ sIn, const unsigned char* __restrict__ Wp,
    const float* __restrict__ Bv, __half* __restrict__ sOut,
    unsigned char* __restrict__ sWbase,
    float* __restrict__ gOut, int row0, int rowlim)
{
    constexpr int NSLAB = K / 16;
    constexpr int NW = NOUT / 8;
    constexpr int NT = NW / 8;
    constexpr int WCH = NW * 2;
    const int tid = threadIdx.x, lane = tid & 31, warp = tid >> 5;
    const int n0 = warp * NW;
    unsigned char* wb = sWbase + warp * WREGION;
    const int g = lane >> 2, tg = lane & 3;
    const int a_row = (lane & 7) + ((lane >> 3) & 1) * 8;
    const int a_k   = (lane >> 4) * 8;
    const int b_n   = ((lane >> 4) & 1) * 8 + (lane & 7);
    const int b_h   = (lane >> 3) & 1;

    auto issue = [&](int s) {
        if (s < NSLAB) {
            const unsigned char* src = Wp + ((size_t)s * NOUT + n0) * 32;
            unsigned char* dst = wb + (s % 3) * WSTAGE;
#pragma unroll
            for (int c = lane; c < WCH; c += 32) {
                uint32_t da = smem_u32(dst + c * 16);
                asm volatile("cp.async.ca.shared.global [%0], [%1], 16;"
                             :: "r"(da), "l"(src + c * 16));
            }
        }
        asm volatile("cp.async.commit_group;");
    };

    if (PRIME) { issue(0); issue(1); issue(2); }
    __syncthreads();   // sIn ready

    float acc[MT][NT][4];
#pragma unroll
    for (int mt = 0; mt < MT; mt++)
#pragma unroll
        for (int nt = 0; nt < NT; nt++)
#pragma unroll
            for (int q = 0; q < 4; q++) acc[mt][nt][q] = 0.f;

    for (int s = 0; s < NSLAB; s++) {
        asm volatile("cp.async.wait_group 2;" ::: "memory");
        __syncwarp();
        const unsigned char* buf = wb + (s % 3) * WSTAGE;
        const int kc = s * 16;
#pragma unroll
        for (int ng = 0; ng < NT / 2; ng++) {
            uint32_t B0, B1, B2, B3;
            ldsm4(B0, B1, B2, B3, smem_u32(buf + bswz(ng * 16 + b_n, b_h)));
#pragma unroll
            for (int mt = 0; mt < MT; mt++) {
                uint32_t A0, A1, A2, A3;
                ldsm4(A0, A1, A2, A3,
                      smem_u32(sIn + (mt * 16 + a_row) * LDIN + kc + a_k));
                mma_f16(acc[mt][2 * ng],     A0, A1, A2, A3, B0, B1);
                mma_f16(acc[mt][2 * ng + 1], A0, A1, A2, A3, B2, B3);
            }
        }
        issue(s + 3);
    }

#pragma unroll
    for (int nt = 0; nt < NT; nt++) {
        int c = n0 + nt * 8 + 2 * tg;
        float b0 = __ldg(Bv + c), b1 = __ldg(Bv + c + 1);
#pragma unroll
        for (int mt = 0; mt < MT; mt++) {
#pragma unroll
            for (int h = 0; h < 2; h++) {
                int r = mt * 16 + g + h * 8;
                float v0 = acc[mt][nt][h * 2 + 0] + b0;
                float v1 = acc[mt][nt][h * 2 + 1] + b1;
                if (RELU) { v0 = fmaxf(v0, 0.f); v1 = fmaxf(v1, 0.f); }
                *(__half2*)(sOut + r * LDOUT + c) = __floats2half2_rn(v0, v1);
                if (gOut != nullptr && row0 + r < rowlim)
                    *(float2*)(gOut + (size_t)(row0 + r) * NOUT + c) =
                        make_float2(v0, v1);
            }
        }
    }
    __syncthreads();
}

// ---------------------------------------------------------------------------
// G2 variant over MT*16 rows: gate dot folded into epilogue (R13-proven).
// ---------------------------------------------------------------------------
template<int K, int LDIN, int MT>
__device__ __forceinline__ void mma_layer_dot(
    const __half* __restrict__ sIn, const unsigned char* __restrict__ Wp,
    const float* __restrict__ Bv, const float* __restrict__ aw3,
    float* __restrict__ sdot, unsigned char* __restrict__ sWbase)
{
    constexpr int NOUT = 128, NSLAB = K / 16, NW = 16, NT = 2, WCH = NW * 2;
    const int tid = threadIdx.x, lane = tid & 31, warp = tid >> 5;
    const int n0 = warp * NW;
    unsigned char* wb = sWbase + warp * WREGION;
    const int g = lane >> 2, tg = lane & 3;
    const int a_row = (lane & 7) + ((lane >> 3) & 1) * 8;
    const int a_k   = (lane >> 4) * 8;
    const int b_n   = ((lane >> 4) & 1) * 8 + (lane & 7);
    const int b_h   = (lane >> 3) & 1;

    auto issue = [&](int s) {
        if (s < NSLAB) {
            const unsigned char* src = Wp + ((size_t)s * NOUT + n0) * 32;
            unsigned char* dst = wb + (s % 3) * WSTAGE;
#pragma unroll
            for (int c = lane; c < WCH; c += 32) {
                uint32_t da = smem_u32(dst + c * 16);
                asm volatile("cp.async.ca.shared.global [%0], [%1], 16;"
                             :: "r"(da), "l"(src + c * 16));
            }
        }
        asm volatile("cp.async.commit_group;");
    };

    issue(0); issue(1); issue(2);
    __syncthreads();

    float acc[MT][NT][4];
#pragma unroll
    for (int mt = 0; mt < MT; mt++)
#pragma unroll
        for (int nt = 0; nt < NT; nt++)
#pragma unroll
            for (int q = 0; q < 4; q++) acc[mt][nt][q] = 0.f;

    for (int s = 0; s < NSLAB; s++) {
        asm volatile("cp.async.wait_group 2;" ::: "memory");
        __syncwarp();
        const unsigned char* buf = wb + (s % 3) * WSTAGE;
        const int kc = s * 16;
        uint32_t B0, B1, B2, B3;
        ldsm4(B0, B1, B2, B3, smem_u32(buf + bswz(b_n, b_h)));
#pragma unroll
        for (int mt = 0; mt < MT; mt++) {
            uint32_t A0, A1, A2, A3;
            ldsm4(A0, A1, A2, A3,
                  smem_u32(sIn + (mt * 16 + a_row) * LDIN + kc + a_k));
            mma_f16(acc[mt][0], A0, A1, A2, A3, B0, B1);
            mma_f16(acc[mt][1], A0, A1, A2, A3, B2, B3);
        }
        issue(s + 3);
    }

    float dp[MT][2];
#pragma unroll
    for (int mt = 0; mt < MT; mt++) { dp[mt][0] = 0.f; dp[mt][1] = 0.f; }
#pragma unroll
    for (int nt = 0; nt < NT; nt++) {
        int c = n0 + nt * 8 + 2 * tg;
        float b0 = __ldg(Bv + c), b1 = __ldg(Bv + c + 1);
        float a0 = __ldg(aw3 + c), a1 = __ldg(aw3 + c + 1);
#pragma unroll
        for (int mt = 0; mt < MT; mt++) {
#pragma unroll
            for (int h = 0; h < 2; h++) {
                float v0 = acc[mt][nt][h * 2 + 0] + b0;
                float v1 = acc[mt][nt][h * 2 + 1] + b1;
                dp[mt][h] += v0 * a0 + v1 * a1;
            }
        }
    }
#pragma unroll
    for (int mt = 0; mt < MT; mt++)
#pragma unroll
        for (int h = 0; h < 2; h++) {
            dp[mt][h] += __shfl_xor_sync(0xffffffffu, dp[mt][h], 1);
            dp[mt][h] += __shfl_xor_sync(0xffffffffu, dp[mt][h], 2);
            if (tg == 0) {
                int r = mt * 16 + g + h * 8;
                sdot[r * 8 + warp] = dp[mt][h];
            }
        }
    __syncthreads();
}

// ---------------------------------------------------------------------------
// Fused pack + init kernel. Swizzled 32B-row layout (R13 version).
// ---------------------------------------------------------------------------
__device__ __forceinline__ void pack_one(const float* src, int idx, int N,
                                         unsigned int off) {
    int k = idx / N, n = idx - k * N;
    int s = k >> 4, h = (k >> 3) & 1, e = k & 7;
    uint32_t b = off + (uint32_t)(s * N + n) * 32u
               + (uint32_t)((h ^ ((n >> 2) & 1)) << 4) + (uint32_t)(e * 2);
    *(__half*)(g_wpack + b) = __float2half_rn(src[idx]);
}
__global__ void pack_init_kernel(
    const float* __restrict__ mw1, const float* __restrict__ mw2,
    const float* __restrict__ mw3, const float* __restrict__ aw1,
    const float* __restrict__ aw2, const float* __restrict__ uw1,
    const float* __restrict__ uw2, const float* __restrict__ uw3, int N)
{
    int idx = blockIdx.x * blockDim.x + threadIdx.x;
    if      (idx <  69632) pack_one(mw1, idx,          256, OFF_MW1);
    else if (idx < 135168) pack_one(mw2, idx -  69632, 256, OFF_MW2);
    else if (idx < 167936) pack_one(mw3, idx - 135168, 128, OFF_MW3);
    else if (idx < 184320) pack_one(aw1, idx - 167936, 128, OFF_AW1);
    else if (idx < 200704) pack_one(aw2, idx - 184320, 128, OFF_AW2);
    else if (idx < 266240) pack_one(uw1, idx - 200704, 256, OFF_UW1);
    else if (idx < 331776) pack_one(uw2, idx - 266240, 256, OFF_UW2);
    else if (idx < 364544) pack_one(uw3, idx - 331776, 128, OFF_UW3);
    if (idx < N * 128) g_aggr[idx] = 0.f;
    if (idx < N) g_denom[idx] = 0.f;
}

// ---------------------------------------------------------------------------
// edge kernel: 128 edges/CTA, 256 threads. L1 weights primed BEFORE gather.
// smem: sA 71680 | sB 67584 | sW 24576 | sdot 4096 | swexp 512 = 168448 B
// ---------------------------------------------------------------------------
__global__ __launch_bounds__(256, 1)
void edge_kernel(
    const float* __restrict__ nodes, const float* __restrict__ edges,
    const int* __restrict__ senders, const int* __restrict__ receivers,
    const float* __restrict__ b1, const float* __restrict__ b2,
    const float* __restrict__ b3, const float* __restrict__ ab1,
    const float* __restrict__ ab2,
    const float* __restrict__ aw3, const float* __restrict__ ab3, int E)
{
    extern __shared__ unsigned char smem[];
    __half* sA = (__half*)smem;                    // stride 280 (or 136)
    __half* sB = (__half*)(smem + 71680);          // stride 264 (or 136)
    unsigned char* sW = smem + 139264;
    float* sdot = (float*)(smem + 163840);         // [128][8]
    float* swexp = (float*)(smem + 167936);        // [128]

    const int tid = threadIdx.x, lane = tid & 31, warp = tid >> 5;
    const int e0 = blockIdx.x * 128;

    // prime L1 weight slabs first: fetch overlaps the gather below
    prime_weights<256>(g_wpack + OFF_MW1, sW);

#pragma unroll
    for (int i = 0; i < 16; i++) {
        int e = warp * 16 + i;
        int eg = e0 + e;
        int egc = eg < E ? eg : E - 1;
        int s = senders[egc], r = receivers[egc];
        __half* dst = sA + e * 280;
        if (lane < 4) {
            float4 v = *(const float4*)(edges + (size_t)egc * 16 + lane * 4);
            *(__half2*)(dst + lane * 4)     = __floats2half2_rn(v.x, v.y);
            *(__half2*)(dst + lane * 4 + 2) = __floats2half2_rn(v.z, v.w);
        }
        float4 vs = *(const float4*)(nodes + (size_t)s * 128 + lane * 4);
        *(__half2*)(dst + 16 + lane * 4)     = __floats2half2_rn(vs.x, vs.y);
        *(__half2*)(dst + 16 + lane * 4 + 2) = __floats2half2_rn(vs.z, vs.w);
        float4 vr = *(const float4*)(nodes + (size_t)r * 128 + lane * 4);
        *(__half2*)(dst + 144 + lane * 4)     = __floats2half2_rn(vr.x, vr.y);
        *(__half2*)(dst + 144 + lane * 4 + 2) = __floats2half2_rn(vr.z, vr.w);
    }

    mma_layer<272, 256, true , 280, 264, 8, false>(sA, g_wpack + OFF_MW1, b1, sB, sW, nullptr, 0, 0);
    mma_layer<256, 256, false, 264, 280, 8, true >(sB, g_wpack + OFF_MW2, b2, sA, sW, nullptr, 0, 0);
    mma_layer<256, 128, false, 280, 136, 8, true >(sA, g_wpack + OFF_MW3, b3, sB, sW, nullptr, 0, 0);
    mma_layer<128, 128, true , 136, 136, 8, true >(sB, g_wpack + OFF_AW1, ab1, sA, sW, nullptr, 0, 0);
    mma_layer_dot<128, 136, 8>(sA, g_wpack + OFF_AW2, ab2, aw3, sdot, sW);

    // finalize gates: w = exp(gate) (max-free softmax)
    if (tid < 128) {
        int eg = e0 + tid;
        float w = 0.f;
        if (eg < E) {
            float gate = __ldg(ab3);
#pragma unroll
            for (int j = 0; j < 8; j++) gate += sdot[tid * 8 + j];
            w = expf(gate);
            atomicAdd(&g_denom[receivers[eg]], w);
        }
        swexp[tid] = w;
    }
    __syncthreads();

    // scatter: aggr[recv] += w * msg (vector red, fp16 msgs in sB stride 136)
#pragma unroll
    for (int i = 0; i < 16; i++) {
        int e = warp * 16 + i;
        int eg = e0 + e;
        if (eg >= E) continue;
        float w = swexp[e];
        int r = receivers[eg];
        __half2 p0 = *(__half2*)(sB + e * 136 + lane * 4);
        __half2 p1 = *(__half2*)(sB + e * 136 + lane * 4 + 2);
        float2 f0 = __half22float2(p0), f1 = __half22float2(p1);
        float* dst = g_aggr + (size_t)r * 128 + lane * 4;
        asm volatile("red.global.add.v4.f32 [%0], {%1, %2, %3, %4};"
                     :: "l"(dst), "f"(w * f0.x), "f"(w * f0.y),
                        "f"(w * f1.x), "f"(w * f1.y) : "memory");
    }
}

// ---------------------------------------------------------------------------
// node kernel: 64-row/2-CTA config, L1 weights primed before gather.
// smem: sA 33792 | sB 33792 | sW 24576 = 92160 B
// ---------------------------------------------------------------------------
__global__ __launch_bounds__(256, 2)
void node_kernel(
    const float* __restrict__ nodes,
    const float* __restrict__ ub1, const float* __restrict__ ub2,
    const float* __restrict__ ub3, float* __restrict__ out, int N)
{
    extern __shared__ unsigned char smem[];
    __half* sA = (__half*)smem;                    // stride 264
    __half* sB = (__half*)(smem + 33792);
    unsigned char* sW = smem + 67584;

    const int tid = threadIdx.x, lane = tid & 31, warp = tid >> 5;
    const int n0 = blockIdx.x * 64;

    prime_weights<256>(g_wpack + OFF_UW1, sW);

#pragma unroll
    for (int i = 0; i < 8; i++) {
        int e = warp * 8 + i;
        int n = n0 + e;
        __half* dst = sA + e * 264;
        if (n < N) {
            float4 v0 = *(const float4*)(nodes + (size_t)n * 128 + lane * 4);
            *(__half2*)(dst + lane * 4)     = __floats2half2_rn(v0.x, v0.y);
            *(__half2*)(dst + lane * 4 + 2) = __floats2half2_rn(v0.z, v0.w);
            float d = g_denom[n];
            float inv = d > 0.f ? 1.f / d : 0.f;
            float4 v1 = *(const float4*)(g_aggr + (size_t)n * 128 + lane * 4);
            *(__half2*)(dst + 128 + lane * 4)     = __floats2half2_rn(inv * v1.x, inv * v1.y);
            *(__half2*)(dst + 128 + lane * 4 + 2) = __floats2half2_rn(inv * v1.z, inv * v1.w);
        } else {
            *(float2*)(dst + lane * 4) = make_float2(0.f, 0.f);
            *(float2*)(dst + 128 + lane * 4) = make_float2(0.f, 0.f);
        }
    }

    mma_layer<256, 256, true , 264, 264, 4, false>(sA, g_wpack + OFF_UW1, ub1, sB, sW, nullptr, 0, 0);
    mma_layer<256, 256, false, 264, 264, 4, true >(sB, g_wpack + OFF_UW2, ub2, sA, sW, nullptr, 0, 0);
    mma_layer<256, 128, false, 264, 136, 4, true >(sA, g_wpack + OFF_UW3, ub3, sB, sW, out, n0, N);
}

// ---------------------------------------------------------------------------
extern "C" void kernel_launch(void* const* d_in, const int* in_sizes, int n_in,
                              void* d_out, int out_size)
{
    const float* nodes     = (const float*)d_in[0];
    const float* edges     = (const float*)d_in[1];
    const int*   senders   = (const int*)  d_in[2];
    const int*   receivers = (const int*)  d_in[3];
    const float* mw1 = (const float*)d_in[4];  const float* mb1 = (const float*)d_in[5];
    const float* mw2 = (const float*)d_in[6];  const float* mb2 = (const float*)d_in[7];
    const float* mw3 = (const float*)d_in[8];  const float* mb3 = (const float*)d_in[9];
    const float* aw1 = (const float*)d_in[10]; const float* ab1 = (const float*)d_in[11];
    const float* aw2 = (const float*)d_in[12]; const float* ab2 = (const float*)d_in[13];
    const float* aw3 = (const float*)d_in[14]; const float* ab3 = (const float*)d_in[15];
    const float* uw1 = (const float*)d_in[16]; const float* ub1 = (const float*)d_in[17];
    const float* uw2 = (const float*)d_in[18]; const float* ub2 = (const float*)d_in[19];
    const float* uw3 = (const float*)d_in[20]; const float* ub3 = (const float*)d_in[21];
    float* out = (float*)d_out;

    const int N = in_sizes[0] / 128;
    const int E = in_sizes[2];

    const int EDGE_SMEM = 168448;
    const int NODE_SMEM = 92160;
    cudaFuncSetAttribute(edge_kernel, cudaFuncAttributeMaxDynamicSharedMemorySize, EDGE_SMEM);
    cudaFuncSetAttribute(node_kernel, cudaFuncAttributeMaxDynamicSharedMemorySize, NODE_SMEM);

    pack_init_kernel<<<(N * 128 + 255) / 256, 256>>>(
        mw1, mw2, mw3, aw1, aw2, uw1, uw2, uw3, N);

    edge_kernel<<<(E + 127) / 128, 256, EDGE_SMEM>>>(
        nodes, edges, senders, receivers,
        mb1, mb2, mb3, ab1, ab2, aw3, ab3, E);

    node_kernel<<<(N + 63) / 64, 256, NODE_SMEM>>>(
        nodes, ub1, ub2, ub3, out, N);
}

// round 16
// speedup vs baseline: 1.1012x; 1.0673x over previous
#include <cuda_runtime.h>
#include <cuda_fp16.h>
#include <cstdint>

#define NMAX 50048
#define EMAX 400000

__device__ float g_denom[NMAX];
__device__ float g_aggr[(size_t)NMAX * 128];
__device__ __align__(16) __half g_ps[(size_t)NMAX * 256];   // nodes @ W1_send
__device__ __align__(16) __half g_pr[(size_t)NMAX * 256];   // nodes @ W1_recv
// packed fp16 weights: per 16-K slab, [NOUT][32B] rows, XOR-swizzled halves
__device__ __align__(16) unsigned char g_wpack[729088];

#define OFF_W1E 0u        // mw1 rows [0,16)    1 slab  (8192)
#define OFF_W1S 8192u     // mw1 rows [16,144)  8 slabs (65536)
#define OFF_W1R 73728u    // mw1 rows [144,272) 8 slabs (65536)
#define OFF_MW2 139264u
#define OFF_MW3 270336u
#define OFF_AW1 335872u
#define OFF_AW2 368640u
#define OFF_UW1 401408u
#define OFF_UW2 532480u
#define OFF_UW3 663552u

__device__ __forceinline__ uint32_t smem_u32(const void* p) {
    return (uint32_t)__cvta_generic_to_shared(p);
}
__device__ __forceinline__ void ldsm4(uint32_t& r0, uint32_t& r1,
                                      uint32_t& r2, uint32_t& r3, uint32_t a) {
    asm volatile("ldmatrix.sync.aligned.m8n8.x4.shared.b16 {%0,%1,%2,%3}, [%4];"
                 : "=r"(r0), "=r"(r1), "=r"(r2), "=r"(r3) : "r"(a));
}
__device__ __forceinline__ void mma_f16(float c[4],
    uint32_t a0, uint32_t a1, uint32_t a2, uint32_t a3, uint32_t b0, uint32_t b1)
{
    asm volatile(
        "mma.sync.aligned.m16n8k16.row.col.f32.f16.f16.f32 "
        "{%0,%1,%2,%3}, {%4,%5,%6,%7}, {%8,%9}, {%0,%1,%2,%3};"
        : "+f"(c[0]), "+f"(c[1]), "+f"(c[2]), "+f"(c[3])
        : "r"(a0), "r"(a1), "r"(a2), "r"(a3), "r"(b0), "r"(b1));
}

#define WSTAGE 1024
#define WREGION 3072

__device__ __forceinline__ uint32_t bswz(int row, int h) {
    return (uint32_t)(row * 32 + ((h ^ ((row >> 2) & 1)) << 4));
}

// Prime: issue slabs 0..2 (3 commit groups; empty beyond NSLAB).
template<int NOUT, int NSLAB>
__device__ __forceinline__ void prime_weights(
    const unsigned char* __restrict__ Wp, unsigned char* __restrict__ sWbase)
{
    constexpr int NW = NOUT / 8;
    constexpr int WCH = NW * 2;
    const int lane = threadIdx.x & 31, warp = threadIdx.x >> 5;
    unsigned char* wb = sWbase + warp * WREGION;
#pragma unroll
    for (int s = 0; s < 3; s++) {
        if (s < NSLAB) {
            const unsigned char* src = Wp + ((size_t)s * NOUT + warp * NW) * 32;
            unsigned char* dst = wb + s * WSTAGE;
#pragma unroll
            for (int c = lane; c < WCH; c += 32) {
                uint32_t da = smem_u32(dst + c * 16);
                asm volatile("cp.async.ca.shared.global [%0], [%1], 16;"
                             :: "r"(da), "l"(src + c * 16));
            }
        }
        asm volatile("cp.async.commit_group;");
    }
}

// ---------------------------------------------------------------------------
// Warp-autonomous fp16 MLP layer over MT*16 rows, 8 warps (R13-proven core).
// ADDIN: epilogue adds the pre-existing fp16 value at sOut (for L1 residual
// P_s+P_r staged into the output buffer). Same-thread read-modify-write.
// ---------------------------------------------------------------------------
template<int K, int NOUT, bool RELU, int LDIN, int LDOUT, int MT, bool PRIME,
         bool ADDIN = false>
__device__ __forceinline__ void mma_layer(
    const __half* __restrict__ sIn, const unsigned char* __restrict__ Wp,
    const float* __restrict__ Bv, __half* __restrict__ sOut,
    unsigned char* __restrict__ sWbase,
    float* __restrict__ gOut, int row0, int rowlim)
{
    constexpr int NSLAB = K / 16;
    constexpr int NW = NOUT / 8;
    constexpr int NT = NW / 8;
    constexpr int WCH = NW * 2;
    const int tid = threadIdx.x, lane = tid & 31, warp = tid >> 5;
    const int n0 = warp * NW;
    unsigned char* wb = sWbase + warp * WREGION;
    const int g = lane >> 2, tg = lane & 3;
    const int a_row = (lane & 7) + ((lane >> 3) & 1) * 8;
    const int a_k   = (lane >> 4) * 8;
    const int b_n   = ((lane >> 4) & 1) * 8 + (lane & 7);
    const int b_h   = (lane >> 3) & 1;

    auto issue = [&](int s) {
        if (s < NSLAB) {
            const unsigned char* src = Wp + ((size_t)s * NOUT + n0) * 32;
            unsigned char* dst = wb + (s % 3) * WSTAGE;
#pragma unroll
            for (int c = lane; c < WCH; c += 32) {
                uint32_t da = smem_u32(dst + c * 16);
                asm volatile("cp.async.ca.shared.global [%0], [%1], 16;"
                             :: "r"(da), "l"(src + c * 16));
            }
        }
        asm volatile("cp.async.commit_group;");
    };

    if (PRIME) { issue(0); issue(1); issue(2); }
    __syncthreads();   // sIn (and ADDIN contents of sOut) ready

    float acc[MT][NT][4];
#pragma unroll
    for (int mt = 0; mt < MT; mt++)
#pragma unroll
        for (int nt = 0; nt < NT; nt++)
#pragma unroll
            for (int q = 0; q < 4; q++) acc[mt][nt][q] = 0.f;

    for (int s = 0; s < NSLAB; s++) {
        asm volatile("cp.async.wait_group 2;" ::: "memory");
        __syncwarp();
        const unsigned char* buf = wb + (s % 3) * WSTAGE;
        const int kc = s * 16;
#pragma unroll
        for (int ng = 0; ng < NT / 2; ng++) {
            uint32_t B0, B1, B2, B3;
            ldsm4(B0, B1, B2, B3, smem_u32(buf + bswz(ng * 16 + b_n, b_h)));
#pragma unroll
            for (int mt = 0; mt < MT; mt++) {
                uint32_t A0, A1, A2, A3;
                ldsm4(A0, A1, A2, A3,
                      smem_u32(sIn + (mt * 16 + a_row) * LDIN + kc + a_k));
                mma_f16(acc[mt][2 * ng],     A0, A1, A2, A3, B0, B1);
                mma_f16(acc[mt][2 * ng + 1], A0, A1, A2, A3, B2, B3);
            }
        }
        issue(s + 3);
    }

#pragma unroll
    for (int nt = 0; nt < NT; nt++) {
        int c = n0 + nt * 8 + 2 * tg;
        float b0 = __ldg(Bv + c), b1 = __ldg(Bv + c + 1);
#pragma unroll
        for (int mt = 0; mt < MT; mt++) {
#pragma unroll
            for (int h = 0; h < 2; h++) {
                int r = mt * 16 + g + h * 8;
                float v0 = acc[mt][nt][h * 2 + 0] + b0;
                float v1 = acc[mt][nt][h * 2 + 1] + b1;
                if (ADDIN) {
                    float2 pf = __half22float2(*(__half2*)(sOut + r * LDOUT + c));
                    v0 += pf.x; v1 += pf.y;
                }
                if (RELU) { v0 = fmaxf(v0, 0.f); v1 = fmaxf(v1, 0.f); }
                *(__half2*)(sOut + r * LDOUT + c) = __floats2half2_rn(v0, v1);
                if (gOut != nullptr && row0 + r < rowlim)
                    *(float2*)(gOut + (size_t)(row0 + r) * NOUT + c) =
                        make_float2(v0, v1);
            }
        }
    }
    __syncthreads();
}

// ---------------------------------------------------------------------------
// G2 variant over MT*16 rows: gate dot folded into epilogue (unchanged).
// ---------------------------------------------------------------------------
template<int K, int LDIN, int MT>
__device__ __forceinline__ void mma_layer_dot(
    const __half* __restrict__ sIn, const unsigned char* __restrict__ Wp,
    const float* __restrict__ Bv, const float* __restrict__ aw3,
    float* __restrict__ sdot, unsigned char* __restrict__ sWbase)
{
    constexpr int NOUT = 128, NSLAB = K / 16, NW = 16, NT = 2, WCH = NW * 2;
    const int tid = threadIdx.x, lane = tid & 31, warp = tid >> 5;
    const int n0 = warp * NW;
    unsigned char* wb = sWbase + warp * WREGION;
    const int g = lane >> 2, tg = lane & 3;
    const int a_row = (lane & 7) + ((lane >> 3) & 1) * 8;
    const int a_k   = (lane >> 4) * 8;
    const int b_n   = ((lane >> 4) & 1) * 8 + (lane & 7);
    const int b_h   = (lane >> 3) & 1;

    auto issue = [&](int s) {
        if (s < NSLAB) {
            const unsigned char* src = Wp + ((size_t)s * NOUT + n0) * 32;
            unsigned char* dst = wb + (s % 3) * WSTAGE;
#pragma unroll
            for (int c = lane; c < WCH; c += 32) {
                uint32_t da = smem_u32(dst + c * 16);
                asm volatile("cp.async.ca.shared.global [%0], [%1], 16;"
                             :: "r"(da), "l"(src + c * 16));
            }
        }
        asm volatile("cp.async.commit_group;");
    };

    issue(0); issue(1); issue(2);
    __syncthreads();

    float acc[MT][NT][4];
#pragma unroll
    for (int mt = 0; mt < MT; mt++)
#pragma unroll
        for (int nt = 0; nt < NT; nt++)
#pragma unroll
            for (int q = 0; q < 4; q++) acc[mt][nt][q] = 0.f;

    for (int s = 0; s < NSLAB; s++) {
        asm volatile("cp.async.wait_group 2;" ::: "memory");
        __syncwarp();
        const unsigned char* buf = wb + (s % 3) * WSTAGE;
        const int kc = s * 16;
        uint32_t B0, B1, B2, B3;
        ldsm4(B0, B1, B2, B3, smem_u32(buf + bswz(b_n, b_h)));
#pragma unroll
        for (int mt = 0; mt < MT; mt++) {
            uint32_t A0, A1, A2, A3;
            ldsm4(A0, A1, A2, A3,
                  smem_u32(sIn + (mt * 16 + a_row) * LDIN + kc + a_k));
            mma_f16(acc[mt][0], A0, A1, A2, A3, B0, B1);
            mma_f16(acc[mt][1], A0, A1, A2, A3, B2, B3);
        }
        issue(s + 3);
    }

    float dp[MT][2];
#pragma unroll
    for (int mt = 0; mt < MT; mt++) { dp[mt][0] = 0.f; dp[mt][1] = 0.f; }
#pragma unroll
    for (int nt = 0; nt < NT; nt++) {
        int c = n0 + nt * 8 + 2 * tg;
        float b0 = __ldg(Bv + c), b1 = __ldg(Bv + c + 1);
        float a0 = __ldg(aw3 + c), a1 = __ldg(aw3 + c + 1);
#pragma unroll
        for (int mt = 0; mt < MT; mt++) {
#pragma unroll
            for (int h = 0; h < 2; h++) {
                float v0 = acc[mt][nt][h * 2 + 0] + b0;
                float v1 = acc[mt][nt][h * 2 + 1] + b1;
                dp[mt][h] += v0 * a0 + v1 * a1;
            }
        }
    }
#pragma unroll
    for (int mt = 0; mt < MT; mt++)
#pragma unroll
        for (int h = 0; h < 2; h++) {
            dp[mt][h] += __shfl_xor_sync(0xffffffffu, dp[mt][h], 1);
            dp[mt][h] += __shfl_xor_sync(0xffffffffu, dp[mt][h], 2);
            if (tg == 0) {
                int r = mt * 16 + g + h * 8;
                sdot[r * 8 + warp] = dp[mt][h];
            }
        }
    __syncthreads();
}

// ---------------------------------------------------------------------------
// proj_layer: out[row][256] (fp16 global) = sIn[64][128] @ W (no bias/relu).
// K=128, MT=4, NT=4 per warp. Same ring discipline as mma_layer.
// ---------------------------------------------------------------------------
__device__ void proj_layer(
    const __half* __restrict__ sIn, const unsigned char* __restrict__ Wp,
    __half* __restrict__ gOut, int row0, int rowlim,
    unsigned char* __restrict__ sWbase)
{
    constexpr int NSLAB = 8, NOUT = 256, NW = 32, NT = 4, WCH = 64, LDIN = 136;
    const int tid = threadIdx.x, lane = tid & 31, warp = tid >> 5;
    const int n0 = warp * NW;
    unsigned char* wb = sWbase + warp * WREGION;
    const int g = lane >> 2, tg = lane & 3;
    const int a_row = (lane & 7) + ((lane >> 3) & 1) * 8;
    const int a_k   = (lane >> 4) * 8;
    const int b_n   = ((lane >> 4) & 1) * 8 + (lane & 7);
    const int b_h   = (lane >> 3) & 1;

    auto issue = [&](int s) {
        if (s < NSLAB) {
            const unsigned char* src = Wp + ((size_t)s * NOUT + n0) * 32;
            unsigned char* dst = wb + (s % 3) * WSTAGE;
#pragma unroll
            for (int c = lane; c < WCH; c += 32) {
                uint32_t da = smem_u32(dst + c * 16);
                asm volatile("cp.async.ca.shared.global [%0], [%1], 16;"
                             :: "r"(da), "l"(src + c * 16));
            }
        }
        asm volatile("cp.async.commit_group;");
    };

    issue(0); issue(1); issue(2);
    __syncthreads();

    float acc[4][NT][4];
#pragma unroll
    for (int mt = 0; mt < 4; mt++)
#pragma unroll
        for (int nt = 0; nt < NT; nt++)
#pragma unroll
            for (int q = 0; q < 4; q++) acc[mt][nt][q] = 0.f;

    for (int s = 0; s < NSLAB; s++) {
        asm volatile("cp.async.wait_group 2;" ::: "memory");
        __syncwarp();
        const unsigned char* buf = wb + (s % 3) * WSTAGE;
        const int kc = s * 16;
#pragma unroll
        for (int ng = 0; ng < NT / 2; ng++) {
            uint32_t B0, B1, B2, B3;
            ldsm4(B0, B1, B2, B3, smem_u32(buf + bswz(ng * 16 + b_n, b_h)));
#pragma unroll
            for (int mt = 0; mt < 4; mt++) {
                uint32_t A0, A1, A2, A3;
                ldsm4(A0, A1, A2, A3,
                      smem_u32(sIn + (mt * 16 + a_row) * LDIN + kc + a_k));
                mma_f16(acc[mt][2 * ng],     A0, A1, A2, A3, B0, B1);
                mma_f16(acc[mt][2 * ng + 1], A0, A1, A2, A3, B2, B3);
            }
        }
        issue(s + 3);
    }

#pragma unroll
    for (int nt = 0; nt < NT; nt++) {
        int c = n0 + nt * 8 + 2 * tg;
#pragma unroll
        for (int mt = 0; mt < 4; mt++) {
#pragma unroll
            for (int h = 0; h < 2; h++) {
                int r = mt * 16 + g + h * 8;
                if (row0 + r < rowlim)
                    *(__half2*)(gOut + (size_t)(row0 + r) * 256 + c) =
                        __floats2half2_rn(acc[mt][nt][h * 2 + 0],
                                          acc[mt][nt][h * 2 + 1]);
            }
        }
    }
    __syncthreads();
}

// ---------------------------------------------------------------------------
// proj_kernel: per-node projections P_s, P_r. 64 nodes/CTA.
// smem: sIn 64*136*2=17408 | sW 24576 = 41984 B
// ---------------------------------------------------------------------------
__global__ __launch_bounds__(256, 2)
void proj_kernel(const float* __restrict__ nodes, int N)
{
    extern __shared__ unsigned char smem[];
    __half* sIn = (__half*)smem;               // stride 136
    unsigned char* sW = smem + 17408;
    const int lane = threadIdx.x & 31, warp = threadIdx.x >> 5;
    const int n0 = blockIdx.x * 64;

#pragma unroll
    for (int i = 0; i < 8; i++) {
        int e = warp * 8 + i;
        int n = n0 + e;
        __half* dst = sIn + e * 136;
        if (n < N) {
            float4 v = *(const float4*)(nodes + (size_t)n * 128 + lane * 4);
            *(__half2*)(dst + lane * 4)     = __floats2half2_rn(v.x, v.y);
            *(__half2*)(dst + lane * 4 + 2) = __floats2half2_rn(v.z, v.w);
        } else {
            *(float2*)(dst + lane * 4) = make_float2(0.f, 0.f);
        }
    }

    proj_layer(sIn, g_wpack + OFF_W1S, g_ps, n0, N, sW);
    proj_layer(sIn, g_wpack + OFF_W1R, g_pr, n0, N, sW);
}

// ---------------------------------------------------------------------------
// Fused pack + init kernel. mw1 split into W1E/W1S/W1R.
// ---------------------------------------------------------------------------
__device__ __forceinline__ void pack_kn(float v, int k, int n, int N,
                                        unsigned int off) {
    int s = k >> 4, h = (k >> 3) & 1, e = k & 7;
    uint32_t b = off + (uint32_t)(s * N + n) * 32u
               + (uint32_t)((h ^ ((n >> 2) & 1)) << 4) + (uint32_t)(e * 2);
    *(__half*)(g_wpack + b) = __float2half_rn(v);
}
__device__ __forceinline__ void pack_one(const float* src, int idx, int N,
                                         unsigned int off) {
    int k = idx / N, n = idx - k * N;
    pack_kn(src[idx], k, n, N, off);
}
__global__ void pack_init_kernel(
    const float* __restrict__ mw1, const float* __restrict__ mw2,
    const float* __restrict__ mw3, const float* __restrict__ aw1,
    const float* __restrict__ aw2, const float* __restrict__ uw1,
    const float* __restrict__ uw2, const float* __restrict__ uw3, int N)
{
    int idx = blockIdx.x * blockDim.x + threadIdx.x;
    if (idx < 69632) {
        int k = idx >> 8, n = idx & 255;
        float v = mw1[idx];
        if      (k < 16)  pack_kn(v, k,       n, 256, OFF_W1E);
        else if (k < 144) pack_kn(v, k - 16,  n, 256, OFF_W1S);
        else              pack_kn(v, k - 144, n, 256, OFF_W1R);
    }
    else if (idx < 135168) pack_one(mw2, idx -  69632, 256, OFF_MW2);
    else if (idx < 167936) pack_one(mw3, idx - 135168, 128, OFF_MW3);
    else if (idx < 184320) pack_one(aw1, idx - 167936, 128, OFF_AW1);
    else if (idx < 200704) pack_one(aw2, idx - 184320, 128, OFF_AW2);
    else if (idx < 266240) pack_one(uw1, idx - 200704, 256, OFF_UW1);
    else if (idx < 331776) pack_one(uw2, idx - 266240, 256, OFF_UW2);
    else if (idx < 364544) pack_one(uw3, idx - 331776, 128, OFF_UW3);
    if (idx < N * 128) g_aggr[idx] = 0.f;
    if (idx < N) g_denom[idx] = 0.f;
}

// ---------------------------------------------------------------------------
// edge kernel: 128 edges/CTA. L1 = 1-slab edge GEMM + staged P_s+P_r add.
// smem: sAe 6144 | sB 67584 | sA 67584 | sW 24576 | sdot 4096 | swexp 512
//     = 170496 B
// ---------------------------------------------------------------------------
__global__ __launch_bounds__(256, 1)
void edge_kernel(
    const float* __restrict__ edges,
    const int* __restrict__ senders, const int* __restrict__ receivers,
    const float* __restrict__ b1, const float* __restrict__ b2,
    const float* __restrict__ b3, const float* __restrict__ ab1,
    const float* __restrict__ ab2,
    const float* __restrict__ aw3, const float* __restrict__ ab3, int E)
{
    extern __shared__ unsigned char smem[];
    __half* sAe = (__half*)smem;                   // [128][24] edge feats
    __half* sB  = (__half*)(smem + 6144);          // stride 264 (or 136)
    __half* sA  = (__half*)(smem + 73728);         // stride 264 (or 136)
    unsigned char* sW = smem + 141312;
    float* sdot = (float*)(smem + 165888);         // [128][8]
    float* swexp = (float*)(smem + 169984);        // [128]

    const int tid = threadIdx.x, lane = tid & 31, warp = tid >> 5;
    const int e0 = blockIdx.x * 128;

    // prime the 1-slab W1E strip (overlaps the gather)
    prime_weights<256, 1>(g_wpack + OFF_W1E, sW);

    // gather: edge feats -> sAe; P_s[s] + P_r[r] (fp32 sum) -> sB
#pragma unroll
    for (int i = 0; i < 16; i++) {
        int e = warp * 16 + i;
        int eg = e0 + e;
        int egc = eg < E ? eg : E - 1;
        int s = senders[egc], r = receivers[egc];
        if (lane < 4) {
            float4 v = *(const float4*)(edges + (size_t)egc * 16 + lane * 4);
            __half* dst = sAe + e * 24 + lane * 4;
            *(__half2*)(dst)     = __floats2half2_rn(v.x, v.y);
            *(__half2*)(dst + 2) = __floats2half2_rn(v.z, v.w);
        }
        uint4 vs = *(const uint4*)(g_ps + (size_t)s * 256 + lane * 8);
        uint4 vr = *(const uint4*)(g_pr + (size_t)r * 256 + lane * 8);
        const __half2* hs = (const __half2*)&vs;
        const __half2* hr = (const __half2*)&vr;
        __half2 o[4];
#pragma unroll
        for (int q = 0; q < 4; q++) {
            float2 a = __half22float2(hs[q]);
            float2 b = __half22float2(hr[q]);
            o[q] = __floats2half2_rn(a.x + b.x, a.y + b.y);
        }
        *(uint4*)(sB + e * 264 + lane * 8) = *(uint4*)o;
    }

    // L1': h1 = relu(E@W1e + b1 + (P_s+P_r))  [1 slab, ADDIN]
    mma_layer< 16, 256, true , 24, 264, 8, false, true>(sAe, g_wpack + OFF_W1E, b1, sB, sW, nullptr, 0, 0);
    mma_layer<256, 256, false, 264, 264, 8, true >(sB, g_wpack + OFF_MW2, b2, sA, sW, nullptr, 0, 0);
    mma_layer<256, 128, false, 264, 136, 8, true >(sA, g_wpack + OFF_MW3, b3, sB, sW, nullptr, 0, 0);
    mma_layer<128, 128, true , 136, 136, 8, true >(sB, g_wpack + OFF_AW1, ab1, sA, sW, nullptr, 0, 0);
    mma_layer_dot<128, 136, 8>(sA, g_wpack + OFF_AW2, ab2, aw3, sdot, sW);

    // finalize gates: w = exp(gate) (max-free softmax)
    if (tid < 128) {
        int eg = e0 + tid;
        float w = 0.f;
        if (eg < E) {
            float gate = __ldg(ab3);
#pragma unroll
            for (int j = 0; j < 8; j++) gate += sdot[tid * 8 + j];
            w = expf(gate);
            atomicAdd(&g_denom[receivers[eg]], w);
        }
        swexp[tid] = w;
    }
    __syncthreads();

    // scatter: aggr[recv] += w * msg (vector red, fp16 msgs in sB stride 136)
#pragma unroll
    for (int i = 0; i < 16; i++) {
        int e = warp * 16 + i;
        int eg = e0 + e;
        if (eg >= E) continue;
        float w = swexp[e];
        int r = receivers[eg];
        __half2 p0 = *(__half2*)(sB + e * 136 + lane * 4);
        __half2 p1 = *(__half2*)(sB + e * 136 + lane * 4 + 2);
        float2 f0 = __half22float2(p0), f1 = __half22float2(p1);
        float* dst = g_aggr + (size_t)r * 128 + lane * 4;
        asm volatile("red.global.add.v4.f32 [%0], {%1, %2, %3, %4};"
                     :: "l"(dst), "f"(w * f0.x), "f"(w * f0.y),
                        "f"(w * f1.x), "f"(w * f1.y) : "memory");
    }
}

// ---------------------------------------------------------------------------
// node kernel: 64-row/2-CTA config (unchanged from R13/R15).
// smem: sA 33792 | sB 33792 | sW 24576 = 92160 B
// ---------------------------------------------------------------------------
__global__ __launch_bounds__(256, 2)
void node_kernel(
    const float* __restrict__ nodes,
    const float* __restrict__ ub1, const float* __restrict__ ub2,
    const float* __restrict__ ub3, float* __restrict__ out, int N)
{
    extern __shared__ unsigned char smem[];
    __half* sA = (__half*)smem;                    // stride 264
    __half* sB = (__half*)(smem + 33792);
    unsigned char* sW = smem + 67584;

    const int tid = threadIdx.x, lane = tid & 31, warp = tid >> 5;
    const int n0 = blockIdx.x * 64;

    prime_weights<256, 16>(g_wpack + OFF_UW1, sW);

#pragma unroll
    for (int i = 0; i < 8; i++) {
        int e = warp * 8 + i;
        int n = n0 + e;
        __half* dst = sA + e * 264;
        if (n < N) {
            float4 v0 = *(const float4*)(nodes + (size_t)n * 128 + lane * 4);
            *(__half2*)(dst + lane * 4)     = __floats2half2_rn(v0.x, v0.y);
            *(__half2*)(dst + lane * 4 + 2) = __floats2half2_rn(v0.z, v0.w);
            float d = g_denom[n];
            float inv = d > 0.f ? 1.f / d : 0.f;
            float4 v1 = *(const float4*)(g_aggr + (size_t)n * 128 + lane * 4);
            *(__half2*)(dst + 128 + lane * 4)     = __floats2half2_rn(inv * v1.x, inv * v1.y);
            *(__half2*)(dst + 128 + lane * 4 + 2) = __floats2half2_rn(inv * v1.z, inv * v1.w);
        } else {
            *(float2*)(dst + lane * 4) = make_float2(0.f, 0.f);
            *(float2*)(dst + 128 + lane * 4) = make_float2(0.f, 0.f);
        }
    }

    mma_layer<256, 256, true , 264, 264, 4, false>(sA, g_wpack + OFF_UW1, ub1, sB, sW, nullptr, 0, 0);
    mma_layer<256, 256, false, 264, 264, 4, true >(sB, g_wpack + OFF_UW2, ub2, sA, sW, nullptr, 0, 0);
    mma_layer<256, 128, false, 264, 136, 4, true >(sA, g_wpack + OFF_UW3, ub3, sB, sW, out, n0, N);
}

// ---------------------------------------------------------------------------
extern "C" void kernel_launch(void* const* d_in, const int* in_sizes, int n_in,
                              void* d_out, int out_size)
{
    const float* nodes     = (const float*)d_in[0];
    const float* edges     = (const float*)d_in[1];
    const int*   senders   = (const int*)  d_in[2];
    const int*   receivers = (const int*)  d_in[3];
    const float* mw1 = (const float*)d_in[4];  const float* mb1 = (const float*)d_in[5];
    const float* mw2 = (const float*)d_in[6];  const float* mb2 = (const float*)d_in[7];
    const float* mw3 = (const float*)d_in[8];  const float* mb3 = (const float*)d_in[9];
    const float* aw1 = (const float*)d_in[10]; const float* ab1 = (const float*)d_in[11];
    const float* aw2 = (const float*)d_in[12]; const float* ab2 = (const float*)d_in[13];
    const float* aw3 = (const float*)d_in[14]; const float* ab3 = (const float*)d_in[15];
    const float* uw1 = (const float*)d_in[16]; const float* ub1 = (const float*)d_in[17];
    const float* uw2 = (const float*)d_in[18]; const float* ub2 = (const float*)d_in[19];
    const float* uw3 = (const float*)d_in[20]; const float* ub3 = (const float*)d_in[21];
    float* out = (float*)d_out;

    const int N = in_sizes[0] / 128;
    const int E = in_sizes[2];

    const int EDGE_SMEM = 170496;
    const int NODE_SMEM = 92160;
    const int PROJ_SMEM = 41984;
    cudaFuncSetAttribute(edge_kernel, cudaFuncAttributeMaxDynamicSharedMemorySize, EDGE_SMEM);
    cudaFuncSetAttribute(node_kernel, cudaFuncAttributeMaxDynamicSharedMemorySize, NODE_SMEM);
    cudaFuncSetAttribute(proj_kernel, cudaFuncAttributeMaxDynamicSharedMemorySize, PROJ_SMEM);

    pack_init_kernel<<<(N * 128 + 255) / 256, 256>>>(
        mw1, mw2, mw3, aw1, aw2, uw1, uw2, uw3, N);

    proj_kernel<<<(N + 63) / 64, 256, PROJ_SMEM>>>(nodes, N);

    edge_kernel<<<(E + 127) / 128, 256, EDGE_SMEM>>>(
        edges, senders, receivers,
        mb1, mb2, mb3, ab1, ab2, aw3, ab3, E);

    node_kernel<<<(N + 63) / 64, 256, NODE_SMEM>>>(
        nodes, ub1, ub2, ub3, out, N);
}